// round 2
// baseline (speedup 1.0000x reference)
#include <cuda_runtime.h>
#include <cuda_bf16.h>

// ---------------------------------------------------------------------------
// Global softmax (unstabilized): out[i] = exp(x[i]) / sum_j exp(x[j])
// N = 33554432 (32M fp32). HBM-bound: 3 passes over data minimum (384 MB).
// Pass 1: per-block partial sums of exp(x)  (128 MB read)
// Pass 2: reduce partials -> inv_sum        (tiny)
// Pass 3: out = exp(x) * inv_sum            (128 MB read + 128 MB write)
// ---------------------------------------------------------------------------

#define NBLOCKS 1184          // 148 SMs * 8 CTAs
#define NTHREADS 256

__device__ float g_partials[NBLOCKS];
__device__ float g_inv_sum;

// ---- Pass 1: partial sums of exp(x) ----
__global__ __launch_bounds__(NTHREADS) void softmax_partial_sum(
    const float* __restrict__ x, int n4)
{
    const float4* __restrict__ x4 = reinterpret_cast<const float4*>(x);
    float acc = 0.0f;
    int stride = gridDim.x * blockDim.x;
    for (int i = blockIdx.x * blockDim.x + threadIdx.x; i < n4; i += stride) {
        float4 v = x4[i];
        acc += __expf(v.x) + __expf(v.y) + __expf(v.z) + __expf(v.w);
    }

    // block reduce
    __shared__ float warp_sums[NTHREADS / 32];
    #pragma unroll
    for (int off = 16; off > 0; off >>= 1)
        acc += __shfl_xor_sync(0xFFFFFFFF, acc, off);
    int lane = threadIdx.x & 31;
    int warp = threadIdx.x >> 5;
    if (lane == 0) warp_sums[warp] = acc;
    __syncthreads();
    if (warp == 0) {
        acc = (lane < NTHREADS / 32) ? warp_sums[lane] : 0.0f;
        #pragma unroll
        for (int off = 16; off > 0; off >>= 1)
            acc += __shfl_xor_sync(0xFFFFFFFF, acc, off);
        if (lane == 0) g_partials[blockIdx.x] = acc;
    }
}

// ---- Pass 2: reduce NBLOCKS partials -> 1/sum ----
__global__ __launch_bounds__(1024) void softmax_reduce_partials()
{
    float acc = 0.0f;
    for (int i = threadIdx.x; i < NBLOCKS; i += 1024)
        acc += g_partials[i];

    __shared__ float warp_sums[32];
    #pragma unroll
    for (int off = 16; off > 0; off >>= 1)
        acc += __shfl_xor_sync(0xFFFFFFFF, acc, off);
    int lane = threadIdx.x & 31;
    int warp = threadIdx.x >> 5;
    if (lane == 0) warp_sums[warp] = acc;
    __syncthreads();
    if (warp == 0) {
        acc = (lane < 32) ? warp_sums[lane] : 0.0f;
        #pragma unroll
        for (int off = 16; off > 0; off >>= 1)
            acc += __shfl_xor_sync(0xFFFFFFFF, acc, off);
        if (lane == 0) g_inv_sum = 1.0f / acc;
    }
}

// ---- Pass 3: normalize ----
__global__ __launch_bounds__(NTHREADS) void softmax_normalize(
    const float* __restrict__ x, float* __restrict__ out, int n4)
{
    const float4* __restrict__ x4 = reinterpret_cast<const float4*>(x);
    float4* __restrict__ o4 = reinterpret_cast<float4*>(out);
    const float inv = g_inv_sum;
    int stride = gridDim.x * blockDim.x;
    for (int i = blockIdx.x * blockDim.x + threadIdx.x; i < n4; i += stride) {
        float4 v = x4[i];
        float4 r;
        r.x = __expf(v.x) * inv;
        r.y = __expf(v.y) * inv;
        r.z = __expf(v.z) * inv;
        r.w = __expf(v.w) * inv;
        o4[i] = r;
    }
}

extern "C" void kernel_launch(void* const* d_in, const int* in_sizes, int n_in,
                              void* d_out, int out_size)
{
    const float* x = (const float*)d_in[0];
    float* out = (float*)d_out;
    int n = in_sizes[0];
    int n4 = n >> 2;   // N = 32M, divisible by 4

    softmax_partial_sum<<<NBLOCKS, NTHREADS>>>(x, n4);
    softmax_reduce_partials<<<1, 1024>>>();
    softmax_normalize<<<NBLOCKS, NTHREADS>>>(x, out, n4);
}

// round 10
// speedup vs baseline: 1.0407x; 1.0407x over previous
#include <cuda_runtime.h>
#include <cuda_bf16.h>

// ---------------------------------------------------------------------------
// Global softmax (unstabilized): out[i] = exp(x[i]) / sum_j exp(x[j])
// N = 32M fp32 (128 MB). HBM-bound.
//
// R2 -> R3 changes:
//  * unroll x2 (two independent float4 LDGs per iter) in both passes  -> MLP 2
//  * normalize pass traverses in REVERSE chunk order: pass 1 leaves the
//    last-touched ~126 MB of input in L2 (L2 = 126 MB), reverse read hits it
//  * output stores use __stcs (streaming / evict-first) so they don't evict
//    the cached input from L2
//  * tiny partial-reduce folded into the top of the normalize kernel
//    (2 launches total instead of 3)
// ---------------------------------------------------------------------------

#define NBLOCKS 1184          // 148 SMs * 8 CTAs, one wave
#define NTHREADS 256

__device__ float g_partials[NBLOCKS];

__device__ __forceinline__ float block_reduce_sum(float v)
{
    __shared__ float warp_sums[NTHREADS / 32];
    #pragma unroll
    for (int off = 16; off > 0; off >>= 1)
        v += __shfl_xor_sync(0xFFFFFFFF, v, off);
    int lane = threadIdx.x & 31;
    int warp = threadIdx.x >> 5;
    if (lane == 0) warp_sums[warp] = v;
    __syncthreads();
    if (warp == 0) {
        v = (lane < NTHREADS / 32) ? warp_sums[lane] : 0.0f;
        #pragma unroll
        for (int off = 16; off > 0; off >>= 1)
            v += __shfl_xor_sync(0xFFFFFFFF, v, off);
    }
    return v;  // valid in warp 0 lane 0
}

// ---- Pass 1: partial sums of exp(x), forward order ----
__global__ __launch_bounds__(NTHREADS) void softmax_partial_sum(
    const float* __restrict__ x, int n4)
{
    const float4* __restrict__ x4 = reinterpret_cast<const float4*>(x);
    const int T = NBLOCKS * NTHREADS;
    int i = blockIdx.x * NTHREADS + threadIdx.x;

    float acc = 0.0f;
    // unroll x2: two independent loads in flight per iteration
    for (; i + T < n4; i += 2 * T) {
        float4 a = x4[i];
        float4 b = x4[i + T];
        acc += __expf(a.x) + __expf(a.y) + __expf(a.z) + __expf(a.w);
        acc += __expf(b.x) + __expf(b.y) + __expf(b.z) + __expf(b.w);
    }
    if (i < n4) {
        float4 a = x4[i];
        acc += __expf(a.x) + __expf(a.y) + __expf(a.z) + __expf(a.w);
    }

    float total = block_reduce_sum(acc);
    if (threadIdx.x == 0) g_partials[blockIdx.x] = total;
}

// ---- Pass 2: reduce partials (per-block, from L2) + normalize in REVERSE ----
__global__ __launch_bounds__(NTHREADS) void softmax_normalize(
    const float* __restrict__ x, float* __restrict__ out, int n4)
{
    // every block independently reduces the 1184 partials (deterministic,
    // identical result in every block; reads are L2 hits)
    float s = 0.0f;
    for (int k = threadIdx.x; k < NBLOCKS; k += NTHREADS)
        s += g_partials[k];
    float total = block_reduce_sum(s);

    __shared__ float s_inv;
    if (threadIdx.x == 0) s_inv = 1.0f / total;
    __syncthreads();
    const float inv = s_inv;

    const float4* __restrict__ x4 = reinterpret_cast<const float4*>(x);
    float4* __restrict__ o4 = reinterpret_cast<float4*>(out);
    const int T = NBLOCKS * NTHREADS;
    int i = blockIdx.x * NTHREADS + threadIdx.x;

    // reverse traversal: j descends from n4-1, hitting the input lines that
    // pass 1 most recently left in L2. Streaming stores keep them resident.
    for (; i + T < n4; i += 2 * T) {
        int j0 = (n4 - 1) - i;
        int j1 = (n4 - 1) - (i + T);
        float4 a = x4[j0];
        float4 b = x4[j1];
        float4 ra, rb;
        ra.x = __expf(a.x) * inv;  ra.y = __expf(a.y) * inv;
        ra.z = __expf(a.z) * inv;  ra.w = __expf(a.w) * inv;
        rb.x = __expf(b.x) * inv;  rb.y = __expf(b.y) * inv;
        rb.z = __expf(b.z) * inv;  rb.w = __expf(b.w) * inv;
        __stcs(&o4[j0], ra);
        __stcs(&o4[j1], rb);
    }
    if (i < n4) {
        int j0 = (n4 - 1) - i;
        float4 a = x4[j0];
        float4 ra;
        ra.x = __expf(a.x) * inv;  ra.y = __expf(a.y) * inv;
        ra.z = __expf(a.z) * inv;  ra.w = __expf(a.w) * inv;
        __stcs(&o4[j0], ra);
    }
}

extern "C" void kernel_launch(void* const* d_in, const int* in_sizes, int n_in,
                              void* d_out, int out_size)
{
    const float* x = (const float*)d_in[0];
    float* out = (float*)d_out;
    int n = in_sizes[0];
    int n4 = n >> 2;   // N = 32M, divisible by 4

    softmax_partial_sum<<<NBLOCKS, NTHREADS>>>(x, n4);
    softmax_normalize<<<NBLOCKS, NTHREADS>>>(x, out, n4);
}

// round 15
// speedup vs baseline: 1.0659x; 1.0242x over previous
#include <cuda_runtime.h>
#include <cuda_bf16.h>

// ---------------------------------------------------------------------------
// Global softmax (unstabilized): out[i] = exp(x[i]) / sum_j exp(x[j])
// N = 32M fp32 (128 MB). HBM-bound, 384 MB total traffic, floor ~55-57 us.
//
// R10 -> R11 changes (post-mortem: reverse-order L2 reuse FAILED, ~30% hit
// only, and reverse indexing cost regs (40 -> occ 61%) + issue slots):
//  * forward traversal in both passes (simple induction, minimal regs)
//  * unroll x4: 4 independent float4 LDGs in flight per thread per iter
//  * normalize: __ldcs reads (x is dead after this pass) + __stcs writes
//  * keep: fused partials-reduce at top of normalize (2 launches total)
// ---------------------------------------------------------------------------

#define NBLOCKS 1184          // 148 SMs * 8 CTAs, one wave
#define NTHREADS 256

__device__ float g_partials[NBLOCKS];

__device__ __forceinline__ float block_reduce_sum(float v)
{
    __shared__ float warp_sums[NTHREADS / 32];
    #pragma unroll
    for (int off = 16; off > 0; off >>= 1)
        v += __shfl_xor_sync(0xFFFFFFFF, v, off);
    int lane = threadIdx.x & 31;
    int warp = threadIdx.x >> 5;
    if (lane == 0) warp_sums[warp] = v;
    __syncthreads();
    if (warp == 0) {
        v = (lane < NTHREADS / 32) ? warp_sums[lane] : 0.0f;
        #pragma unroll
        for (int off = 16; off > 0; off >>= 1)
            v += __shfl_xor_sync(0xFFFFFFFF, v, off);
    }
    return v;  // valid in warp 0 lane 0
}

__device__ __forceinline__ float exp_sum4(float4 v)
{
    return (__expf(v.x) + __expf(v.y)) + (__expf(v.z) + __expf(v.w));
}

// ---- Pass 1: partial sums of exp(x) ----
__global__ __launch_bounds__(NTHREADS) void softmax_partial_sum(
    const float* __restrict__ x, int n4)
{
    const float4* __restrict__ x4 = reinterpret_cast<const float4*>(x);
    const int T = NBLOCKS * NTHREADS;
    int i = blockIdx.x * NTHREADS + threadIdx.x;

    float acc0 = 0.0f, acc1 = 0.0f, acc2 = 0.0f, acc3 = 0.0f;
    // unroll x4: four independent loads in flight per iteration
    for (; i + 3 * T < n4; i += 4 * T) {
        float4 a = x4[i];
        float4 b = x4[i + T];
        float4 c = x4[i + 2 * T];
        float4 d = x4[i + 3 * T];
        acc0 += exp_sum4(a);
        acc1 += exp_sum4(b);
        acc2 += exp_sum4(c);
        acc3 += exp_sum4(d);
    }
    for (; i < n4; i += T)
        acc0 += exp_sum4(x4[i]);

    float total = block_reduce_sum((acc0 + acc1) + (acc2 + acc3));
    if (threadIdx.x == 0) g_partials[blockIdx.x] = total;
}

// ---- Pass 2: reduce partials (from L2) + normalize, forward ----
__global__ __launch_bounds__(NTHREADS) void softmax_normalize(
    const float* __restrict__ x, float* __restrict__ out, int n4)
{
    // every block independently reduces the 1184 partials (deterministic,
    // identical result in every block; reads are L2 hits)
    float s = 0.0f;
    for (int k = threadIdx.x; k < NBLOCKS; k += NTHREADS)
        s += g_partials[k];
    float total = block_reduce_sum(s);

    __shared__ float s_inv;
    if (threadIdx.x == 0) s_inv = 1.0f / total;
    __syncthreads();
    const float inv = s_inv;

    const float4* __restrict__ x4 = reinterpret_cast<const float4*>(x);
    float4* __restrict__ o4 = reinterpret_cast<float4*>(out);
    const int T = NBLOCKS * NTHREADS;
    int i = blockIdx.x * NTHREADS + threadIdx.x;

    for (; i + 3 * T < n4; i += 4 * T) {
        float4 a = __ldcs(&x4[i]);
        float4 b = __ldcs(&x4[i + T]);
        float4 c = __ldcs(&x4[i + 2 * T]);
        float4 d = __ldcs(&x4[i + 3 * T]);
        float4 ra, rb, rc, rd;
        ra.x = __expf(a.x) * inv;  ra.y = __expf(a.y) * inv;
        ra.z = __expf(a.z) * inv;  ra.w = __expf(a.w) * inv;
        rb.x = __expf(b.x) * inv;  rb.y = __expf(b.y) * inv;
        rb.z = __expf(b.z) * inv;  rb.w = __expf(b.w) * inv;
        rc.x = __expf(c.x) * inv;  rc.y = __expf(c.y) * inv;
        rc.z = __expf(c.z) * inv;  rc.w = __expf(c.w) * inv;
        rd.x = __expf(d.x) * inv;  rd.y = __expf(d.y) * inv;
        rd.z = __expf(d.z) * inv;  rd.w = __expf(d.w) * inv;
        __stcs(&o4[i],         ra);
        __stcs(&o4[i + T],     rb);
        __stcs(&o4[i + 2 * T], rc);
        __stcs(&o4[i + 3 * T], rd);
    }
    for (; i < n4; i += T) {
        float4 a = __ldcs(&x4[i]);
        float4 ra;
        ra.x = __expf(a.x) * inv;  ra.y = __expf(a.y) * inv;
        ra.z = __expf(a.z) * inv;  ra.w = __expf(a.w) * inv;
        __stcs(&o4[i], ra);
    }
}

extern "C" void kernel_launch(void* const* d_in, const int* in_sizes, int n_in,
                              void* d_out, int out_size)
{
    const float* x = (const float*)d_in[0];
    float* out = (float*)d_out;
    int n = in_sizes[0];
    int n4 = n >> 2;   // N = 32M, divisible by 4

    softmax_partial_sum<<<NBLOCKS, NTHREADS>>>(x, n4);
    softmax_normalize<<<NBLOCKS, NTHREADS>>>(x, out, n4);
}